// round 10
// baseline (speedup 1.0000x reference)
#include <cuda_runtime.h>
#include <math.h>

#define TPB  512
#define NW   (TPB / 32)   // 16 warps
#define KC   10           // n_point_candidate
#define NKP  9            // 8 keypoints + 1 center
#define CAP  1024         // collected-candidate capacity (expected ~12 used)
#define REGC 6            // float4 per thread held in registers (n <= TPB*REGC*4)

// order-preserving float -> uint key (works for all finite floats)
__device__ __forceinline__ unsigned fkey(float x) {
    unsigned u = __float_as_uint(x);
    return (u & 0x80000000u) ? ~u : (u | 0x80000000u);
}
__device__ __forceinline__ float funkey(unsigned k) {
    return __uint_as_float((k & 0x80000000u) ? (k & 0x7FFFFFFFu) : ~k);
}

// A&S 4.4.46 polynomial acos, |err| ~ 2e-8 rad, branch-free-ish
__device__ __forceinline__ float acos_poly(float x) {
    float ax = fabsf(x);
    float p = -0.0012624911f;
    p = p * ax + 0.0066700901f;
    p = p * ax - 0.0170881256f;
    p = p * ax + 0.0308918810f;
    p = p * ax - 0.0501743046f;
    p = p * ax + 0.0889789874f;
    p = p * ax - 0.2145988016f;
    p = p * ax + 1.5707963050f;
    float r = p * sqrtf(fmaxf(1.0f - ax, 0.0f));
    return (x >= 0.0f) ? r : (3.14159265358979f - r);
}

// eigenvector of symmetric K for eigenvalue lam: largest cross product of rows of K-lam*I
__device__ __forceinline__ void eigvec3(const float K[3][3], float lam, float v[3]) {
    float a00 = K[0][0] - lam, a11 = K[1][1] - lam, a22 = K[2][2] - lam;
    float a01 = K[0][1], a02 = K[0][2], a12 = K[1][2];
    float c0x = a01*a12 - a02*a11, c0y = a02*a01 - a00*a12, c0z = a00*a11 - a01*a01;
    float c1x = a01*a22 - a02*a12, c1y = a02*a02 - a00*a22, c1z = a00*a12 - a01*a02;
    float c2x = a11*a22 - a12*a12, c2y = a12*a02 - a01*a22, c2z = a01*a12 - a11*a02;
    float n0 = c0x*c0x + c0y*c0y + c0z*c0z;
    float n1 = c1x*c1x + c1y*c1y + c1z*c1z;
    float n2 = c2x*c2x + c2y*c2y + c2z*c2z;
    float bx = c0x, by = c0y, bz = c0z, bn = n0;
    if (n1 > bn) { bx = c1x; by = c1y; bz = c1z; bn = n1; }
    if (n2 > bn) { bx = c2x; by = c2y; bz = c2z; bn = n2; }
    float inv = (bn > 1e-30f) ? __frsqrt_rn(bn) : 0.0f;
    v[0] = bx * inv; v[1] = by * inv; v[2] = bz * inv;
}

__global__ __launch_bounds__(TPB)
void pose_fused_kernel(const float* __restrict__ pcld,
                       const float* __restrict__ kpts,
                       const float* __restrict__ cpt,
                       const float* __restrict__ seg,
                       const float* __restrict__ mesh,
                       float* __restrict__ outR,
                       float* __restrict__ outT,
                       float* __restrict__ outV,
                       int n)
{
    const int b   = blockIdx.x;
    const int tid = threadIdx.x;

    __shared__ unsigned wmaxk[NW];
    __shared__ float sT;
    __shared__ int   cnt;
    __shared__ float smesh[NKP * 3];
    __shared__ float cv[CAP];
    __shared__ int   ci[CAP];
    __shared__ int   topi[KC];
    __shared__ float cand[NKP][KC][3];
    __shared__ float voted[NKP][3];
    __shared__ float sC[6];        // cA[0..2], cB[0..2]
    __shared__ float sH[9];        // H row-major
    __shared__ float sV2[3];       // second eigenvector

    // issue the tiny mesh load FIRST so its DRAM latency hides under the seg epoch
    if (tid < NKP * 3) smesh[tid] = mesh[(long long)b * NKP * 3 + tid];
    if (tid == 0) cnt = 0;

    const float*  segb = seg + (long long)b * n;
    const int     nf4  = n >> 2;
    const float4* seg4 = (const float4*)segb;
    const int     regEnd = TPB * REGC;      // float4 indices covered by registers

    // ---- single load pass: everything into registers (6 independent loads) ----
    float4 buf[REGC];
#pragma unroll
    for (int j = 0; j < REGC; j++) {
        int i4 = tid + j * TPB;
        buf[j] = (i4 < nf4) ? seg4[i4]
                            : make_float4(-INFINITY, -INFINITY, -INFINITY, -INFINITY);
    }

    float m = -INFINITY;
#pragma unroll
    for (int j = 0; j < REGC; j++)
        m = fmaxf(m, fmaxf(fmaxf(buf[j].x, buf[j].y), fmaxf(buf[j].z, buf[j].w)));

    // fallback for n beyond register capacity (not taken at n = 12288)
    for (int i4 = regEnd + tid; i4 < nf4; i4 += TPB) {
        float4 v = seg4[i4];
        m = fmaxf(m, fmaxf(fmaxf(v.x, v.y), fmaxf(v.z, v.w)));
    }
    for (int i = (nf4 << 2) + tid; i < n; i += TPB)
        m = fmaxf(m, segb[i]);

    // ---- warp max via single REDUX on order-preserving key ----
    unsigned mk = __reduce_max_sync(0xFFFFFFFFu, fkey(m));
    if ((tid & 31) == 0) wmaxk[tid >> 5] = mk;
    __syncthreads();

    // threshold T = 10th-largest warp max (rank KC-1). 10 disjoint warps each
    // hold >=1 element >= T  =>  global top-10 are all >= T.
    if (tid < NW) {
        unsigned v = wmaxk[tid];
        int rank = 0;
#pragma unroll
        for (int j = 0; j < NW; j++) {
            unsigned vj = wmaxk[j];
            rank += (vj > v) || (vj == v && j < tid);
        }
        if (rank == KC - 1) sT = funkey(v);
    }
    __syncthreads();
    const float T = sT;

    // ---- filter pass from REGISTERS (no memory traffic) ----
#pragma unroll
    for (int j = 0; j < REGC; j++) {
        int i4 = tid + j * TPB;
        float xs[4] = {buf[j].x, buf[j].y, buf[j].z, buf[j].w};
#pragma unroll
        for (int c = 0; c < 4; c++) {
            if (xs[c] >= T) {
                int s = atomicAdd(&cnt, 1);
                if (s < CAP) { cv[s] = xs[c]; ci[s] = (i4 << 2) + c; }
            }
        }
    }
    // fallback ranges rescan memory (not taken at n = 12288)
    for (int i4 = regEnd + tid; i4 < nf4; i4 += TPB) {
        float4 v = seg4[i4];
        float xs[4] = {v.x, v.y, v.z, v.w};
#pragma unroll
        for (int c = 0; c < 4; c++) {
            if (xs[c] >= T) {
                int s = atomicAdd(&cnt, 1);
                if (s < CAP) { cv[s] = xs[c]; ci[s] = (i4 << 2) + c; }
            }
        }
    }
    for (int i = (nf4 << 2) + tid; i < n; i += TPB) {
        float x = segb[i];
        if (x >= T) {
            int s = atomicAdd(&cnt, 1);
            if (s < CAP) { cv[s] = x; ci[s] = i; }
        }
    }
    __syncthreads();

    // exact top-10 set by rank-counting among the ~12 collected
    {
        int mC = min(cnt, CAP);
        for (int i = tid; i < mC; i += TPB) {
            float v = cv[i]; int id = ci[i];
            int rank = 0;
            for (int j = 0; j < mC; j++) {
                float vj = cv[j];
                rank += (vj > v) || (vj == v && ci[j] < id);
            }
            if (rank < KC) topi[rank] = id;
        }
    }
    __syncthreads();

    // ---------------- build candidates (90 threads) ----------------
    if (tid < NKP * KC) {
        int i  = tid / KC;           // keypoint
        int j  = tid % KC;           // candidate
        int id = topi[j];
        const float* p = pcld + ((long long)b * n + id) * 3;
        const float* o = (i < 8)
            ? (kpts + (((long long)b * n + id) * 8 + i) * 3)
            : (cpt  + ((long long)b * n + id) * 3);
        cand[i][j][0] = p[0] + o[0];
        cand[i][j][1] = p[1] + o[1];
        cand[i][j][2] = p[2] + o[2];
    }
    __syncthreads();

    // ================= warp-0 tail: cluster -> centroids -> H -> eigen -> R,t ====
    if (tid < 32) {
        const int lane = tid;

        // ---- clustering with std filter (lanes 0..8) ----
        if (lane < NKP) {
            float m0 = 0.f, m1 = 0.f, m2 = 0.f;
#pragma unroll
            for (int j = 0; j < KC; j++) { m0 += cand[lane][j][0]; m1 += cand[lane][j][1]; m2 += cand[lane][j][2]; }
            m0 *= 0.1f; m1 *= 0.1f; m2 *= 0.1f;
            float v0 = 0.f, v1 = 0.f, v2 = 0.f;
#pragma unroll
            for (int j = 0; j < KC; j++) {
                float d0 = cand[lane][j][0] - m0, d1 = cand[lane][j][1] - m1, d2 = cand[lane][j][2] - m2;
                v0 += d0 * d0; v1 += d1 * d1; v2 += d2 * d2;
            }
            float s0 = sqrtf(v0 * 0.1f), s1 = sqrtf(v1 * 0.1f), s2 = sqrtf(v2 * 0.1f);
            float a0 = 0.f, a1 = 0.f, a2 = 0.f, cc = 0.f;
#pragma unroll
            for (int j = 0; j < KC; j++) {
                float c0 = cand[lane][j][0], c1 = cand[lane][j][1], c2 = cand[lane][j][2];
                bool in = (fabsf(c0 - m0) <= s0) && (fabsf(c1 - m1) <= s1) && (fabsf(c2 - m2) <= s2);
                if (in) { cc += 1.f; a0 += c0; a1 += c1; a2 += c2; }
            }
            float inv = __fdividef(1.0f, cc + 1e-6f);
            float w0 = a0 * inv, w1 = a1 * inv, w2 = a2 * inv;
            voted[lane][0] = w0; voted[lane][1] = w1; voted[lane][2] = w2;
            long long vo = ((long long)b * NKP + lane) * 3;
            outV[vo + 0] = w0; outV[vo + 1] = w1; outV[vo + 2] = w2;
        }
        __syncwarp();

        // ---- centroids: lanes 0-2 -> cA axis, lanes 3-5 -> cB axis ----
        if (lane < 6) {
            int ax = lane % 3;
            float s = 0.f;
            if (lane < 3) {
#pragma unroll
                for (int i = 0; i < NKP; i++) s += smesh[i * 3 + ax];
            } else {
#pragma unroll
                for (int i = 0; i < NKP; i++) s += voted[i][ax];
            }
            sC[lane] = s * (1.0f / 9.0f);
        }
        __syncwarp();

        // ---- H entries on 9 lanes: H[r][c] = sum_i (A_i[r]-cA[r])(B_i[c]-cB[c]) ----
        if (lane < 9) {
            int r = lane / 3, c = lane % 3;
            float car = sC[r], cbc = sC[3 + c];
            float s = 0.f;
#pragma unroll
            for (int i = 0; i < NKP; i++)
                s += (smesh[i * 3 + r] - car) * (voted[i][c] - cbc);
            sH[lane] = s;
        }
        __syncwarp();

        // ---- eigen decomposition: lanes 0 and 1 run in lockstep, lane k gets e_{k+1} ----
        float v1[3] = {1.f, 0.f, 0.f};
        float H[3][3];
        if (lane < 2) {
#pragma unroll
            for (int r = 0; r < 3; r++)
#pragma unroll
                for (int c = 0; c < 3; c++)
                    H[r][c] = sH[r * 3 + c];

            float K[3][3];
#pragma unroll
            for (int r = 0; r < 3; r++)
#pragma unroll
                for (int c = 0; c < 3; c++)
                    K[r][c] = H[0][r]*H[0][c] + H[1][r]*H[1][c] + H[2][r]*H[2][c];

            float vv[3] = { (lane == 0) ? 1.f : 0.f, (lane == 0) ? 0.f : 1.f, 0.f };
            float q  = (K[0][0] + K[1][1] + K[2][2]) * (1.0f / 3.0f);
            float p1 = K[0][1]*K[0][1] + K[0][2]*K[0][2] + K[1][2]*K[1][2];
            float b0 = K[0][0] - q, b1 = K[1][1] - q, b2 = K[2][2] - q;
            float p2 = b0*b0 + b1*b1 + b2*b2 + 2.0f * p1;
            if (p2 > 1e-30f) {
                float pp   = p2 * (1.0f / 6.0f);
                float invp = __frsqrt_rn(pp);
                float p    = pp * invp;                 // sqrt(p2/6)
                float detB = b0 * (b1*b2 - K[1][2]*K[1][2])
                           - K[0][1] * (K[0][1]*b2 - K[1][2]*K[0][2])
                           + K[0][2] * (K[0][1]*K[1][2] - b1*K[0][2]);
                float r = detB * 0.5f * invp * invp * invp;
                r = fminf(1.0f, fmaxf(-1.0f, r));
                float phi = acos_poly(r) * (1.0f / 3.0f);
                float e1 = q + 2.0f * p * __cosf(phi);
                float e3 = q + 2.0f * p * __cosf(phi + 2.0943951023931953f);
                float e2 = 3.0f * q - e1 - e3;
                float lam = (lane == 0) ? e1 : e2;
                eigvec3(K, lam, vv);
            }
            if (lane == 1) { sV2[0] = vv[0]; sV2[1] = vv[1]; sV2[2] = vv[2]; }
            else           { v1[0] = vv[0];  v1[1] = vv[1];  v1[2] = vv[2]; }
        }
        __syncwarp();

        // ---- final serial stretch on lane 0 ----
        if (lane == 0) {
            float v2[3] = { sV2[0], sV2[1], sV2[2] };
            // re-orthogonalize v2 against v1 (robust near-degenerate gaps)
            float d = v2[0]*v1[0] + v2[1]*v1[1] + v2[2]*v1[2];
            v2[0] -= d * v1[0]; v2[1] -= d * v1[1]; v2[2] -= d * v1[2];
            float nn = v2[0]*v2[0] + v2[1]*v2[1] + v2[2]*v2[2];
            float ii = (nn > 1e-30f) ? __frsqrt_rn(nn) : 0.0f;
            v2[0] *= ii; v2[1] *= ii; v2[2] *= ii;

            float v3[3] = { v1[1]*v2[2] - v1[2]*v2[1],
                            v1[2]*v2[0] - v1[0]*v2[2],
                            v1[0]*v2[1] - v1[1]*v2[0] };

            float u1[3], u2[3], u3[3];
#pragma unroll
            for (int r = 0; r < 3; r++) u1[r] = H[r][0]*v1[0] + H[r][1]*v1[1] + H[r][2]*v1[2];
            float d1 = u1[0]*u1[0] + u1[1]*u1[1] + u1[2]*u1[2];
            float in1 = (d1 > 1e-30f) ? __frsqrt_rn(d1) : 0.0f;
            u1[0] *= in1; u1[1] *= in1; u1[2] *= in1;

#pragma unroll
            for (int r = 0; r < 3; r++) u2[r] = H[r][0]*v2[0] + H[r][1]*v2[1] + H[r][2]*v2[2];
            float d12 = u2[0]*u1[0] + u2[1]*u1[1] + u2[2]*u1[2];
            u2[0] -= d12 * u1[0]; u2[1] -= d12 * u1[1]; u2[2] -= d12 * u1[2];
            float d2 = u2[0]*u2[0] + u2[1]*u2[1] + u2[2]*u2[2];
            float in2 = (d2 > 1e-30f) ? __frsqrt_rn(d2) : 0.0f;
            u2[0] *= in2; u2[1] *= in2; u2[2] *= in2;

            u3[0] = u1[1]*u2[2] - u1[2]*u2[1];
            u3[1] = u1[2]*u2[0] - u1[0]*u2[2];
            u3[2] = u1[0]*u2[1] - u1[1]*u2[0];

            float R[3][3];
#pragma unroll
            for (int r = 0; r < 3; r++)
#pragma unroll
                for (int c = 0; c < 3; c++)
                    R[r][c] = v1[r]*u1[c] + v2[r]*u2[c] + v3[r]*u3[c];

            float det = R[0][0]*(R[1][1]*R[2][2] - R[1][2]*R[2][1])
                      - R[0][1]*(R[1][0]*R[2][2] - R[1][2]*R[2][0])
                      + R[0][2]*(R[1][0]*R[2][1] - R[1][1]*R[2][0]);
            if (det < 0.0f) {
#pragma unroll
                for (int r = 0; r < 3; r++)
#pragma unroll
                    for (int c = 0; c < 3; c++)
                        R[r][c] -= 2.0f * v3[r] * u3[c];
            }

            long long ro = (long long)b * 9;
#pragma unroll
            for (int r = 0; r < 3; r++)
#pragma unroll
                for (int c = 0; c < 3; c++)
                    outR[ro + r*3 + c] = R[r][c];

            long long to = (long long)b * 3;
#pragma unroll
            for (int c = 0; c < 3; c++) {
                float tc = sC[3 + c] - (R[c][0]*sC[0] + R[c][1]*sC[1] + R[c][2]*sC[2]);
                outT[to + c] = tc;
            }
        }
    }
}

extern "C" void kernel_launch(void* const* d_in, const int* in_sizes, int n_in,
                              void* d_out, int out_size)
{
    const float* pcld = (const float*)d_in[0];  // [b,n,3]
    const float* kpts = (const float*)d_in[1];  // [b,n,8,3]
    const float* cpt  = (const float*)d_in[2];  // [b,n,1,3]
    const float* seg  = (const float*)d_in[3];  // [b,n,1]
    const float* mesh = (const float*)d_in[4];  // [b,9,3]

    int b = in_sizes[4] / 27;       // mesh is b*9*3
    int n = in_sizes[3] / b;        // seg is b*n

    float* out  = (float*)d_out;
    float* outR = out;                      // b*9
    float* outT = out + (long long)b * 9;   // b*3
    float* outV = out + (long long)b * 12;  // b*27

    pose_fused_kernel<<<b, TPB>>>(pcld, kpts, cpt, seg, mesh, outR, outT, outV, n);
}

// round 13
// speedup vs baseline: 1.4982x; 1.4982x over previous
#include <cuda_runtime.h>
#include <math.h>

#define TPB  1024
#define NW   (TPB / 32)   // 32 warps
#define KC   10           // n_point_candidate
#define NKP  9            // 8 keypoints + 1 center
#define CAP  1024         // collected-candidate capacity (expected ~12 used)
#define REGC 3            // float4 per thread held in registers (n <= TPB*REGC*4)

// order-preserving float -> uint key (works for all finite floats)
__device__ __forceinline__ unsigned fkey(float x) {
    unsigned u = __float_as_uint(x);
    return (u & 0x80000000u) ? ~u : (u | 0x80000000u);
}
__device__ __forceinline__ float funkey(unsigned k) {
    return __uint_as_float((k & 0x80000000u) ? (k & 0x7FFFFFFFu) : ~k);
}

// A&S 4.4.46 polynomial acos, |err| ~ 2e-8 rad
__device__ __forceinline__ float acos_poly(float x) {
    float ax = fabsf(x);
    float p = -0.0012624911f;
    p = p * ax + 0.0066700901f;
    p = p * ax - 0.0170881256f;
    p = p * ax + 0.0308918810f;
    p = p * ax - 0.0501743046f;
    p = p * ax + 0.0889789874f;
    p = p * ax - 0.2145988016f;
    p = p * ax + 1.5707963050f;
    float r = p * sqrtf(fmaxf(1.0f - ax, 0.0f));
    return (x >= 0.0f) ? r : (3.14159265358979f - r);
}

// eigenvector of symmetric K for eigenvalue lam: largest cross product of rows of K-lam*I
__device__ __forceinline__ void eigvec3(const float K[3][3], float lam, float v[3]) {
    float a00 = K[0][0] - lam, a11 = K[1][1] - lam, a22 = K[2][2] - lam;
    float a01 = K[0][1], a02 = K[0][2], a12 = K[1][2];
    float c0x = a01*a12 - a02*a11, c0y = a02*a01 - a00*a12, c0z = a00*a11 - a01*a01;
    float c1x = a01*a22 - a02*a12, c1y = a02*a02 - a00*a22, c1z = a00*a12 - a01*a02;
    float c2x = a11*a22 - a12*a12, c2y = a12*a02 - a01*a22, c2z = a01*a12 - a11*a02;
    float n0 = c0x*c0x + c0y*c0y + c0z*c0z;
    float n1 = c1x*c1x + c1y*c1y + c1z*c1z;
    float n2 = c2x*c2x + c2y*c2y + c2z*c2z;
    float bx = c0x, by = c0y, bz = c0z, bn = n0;
    if (n1 > bn) { bx = c1x; by = c1y; bz = c1z; bn = n1; }
    if (n2 > bn) { bx = c2x; by = c2y; bz = c2z; bn = n2; }
    float inv = (bn > 1e-30f) ? __frsqrt_rn(bn) : 0.0f;
    v[0] = bx * inv; v[1] = by * inv; v[2] = bz * inv;
}

__global__ __launch_bounds__(TPB)
void pose_fused_kernel(const float* __restrict__ pcld,
                       const float* __restrict__ kpts,
                       const float* __restrict__ cpt,
                       const float* __restrict__ seg,
                       const float* __restrict__ mesh,
                       float* __restrict__ outR,
                       float* __restrict__ outT,
                       float* __restrict__ outV,
                       int n)
{
    const int b   = blockIdx.x;
    const int tid = threadIdx.x;

    __shared__ unsigned wmaxk[NW];
    __shared__ float sT;
    __shared__ int   cnt;
    __shared__ float smesh[NKP * 3];
    __shared__ float cv[CAP];
    __shared__ int   ci[CAP];
    __shared__ int   topi[KC];
    __shared__ float cand[NKP][KC][3];
    __shared__ float voted[NKP][3];

    // issue the tiny mesh load FIRST so its DRAM latency hides under the seg epoch
    if (tid < NKP * 3) smesh[tid] = mesh[(long long)b * NKP * 3 + tid];
    if (tid == 0) cnt = 0;

    const float*  segb = seg + (long long)b * n;
    const int     nf4  = n >> 2;
    const float4* seg4 = (const float4*)segb;
    const int     regEnd = TPB * REGC;      // float4 indices covered by registers

    // ---- single load pass: everything into registers (3 independent LDG.128) ----
    float4 buf[REGC];
#pragma unroll
    for (int j = 0; j < REGC; j++) {
        int i4 = tid + j * TPB;
        buf[j] = (i4 < nf4) ? seg4[i4]
                            : make_float4(-INFINITY, -INFINITY, -INFINITY, -INFINITY);
    }

    // per-vector maxes (reused by the filter) + thread max
    float v4m[REGC];
#pragma unroll
    for (int j = 0; j < REGC; j++)
        v4m[j] = fmaxf(fmaxf(buf[j].x, buf[j].y), fmaxf(buf[j].z, buf[j].w));
    float m = v4m[0];
#pragma unroll
    for (int j = 1; j < REGC; j++) m = fmaxf(m, v4m[j]);

    // fallback for n beyond register capacity (not taken at n = 12288)
    for (int i4 = regEnd + tid; i4 < nf4; i4 += TPB) {
        float4 v = seg4[i4];
        m = fmaxf(m, fmaxf(fmaxf(v.x, v.y), fmaxf(v.z, v.w)));
    }
    for (int i = (nf4 << 2) + tid; i < n; i += TPB)
        m = fmaxf(m, segb[i]);

    // ---- warp max via single REDUX on order-preserving key ----
    unsigned mk = __reduce_max_sync(0xFFFFFFFFu, fkey(m));
    if ((tid & 31) == 0) wmaxk[tid >> 5] = mk;
    __syncthreads();

    // threshold T = 10th-largest warp max (rank KC-1). 10 disjoint warps each
    // hold >=1 element >= T  =>  global top-10 are all >= T.
    if (tid < NW) {
        unsigned v = wmaxk[tid];
        int rank = 0;
#pragma unroll
        for (int j = 0; j < NW; j++) {
            unsigned vj = wmaxk[j];
            rank += (vj > v) || (vj == v && j < tid);
        }
        if (rank == KC - 1) sT = funkey(v);
    }
    __syncthreads();
    const float T = sT;

    // ---- filter pass from REGISTERS, per-vector skip (no memory traffic) ----
#pragma unroll
    for (int j = 0; j < REGC; j++) {
        if (v4m[j] >= T) {
            int i4 = tid + j * TPB;
            float xs[4] = {buf[j].x, buf[j].y, buf[j].z, buf[j].w};
#pragma unroll
            for (int c = 0; c < 4; c++) {
                if (xs[c] >= T) {
                    int s = atomicAdd(&cnt, 1);
                    if (s < CAP) { cv[s] = xs[c]; ci[s] = (i4 << 2) + c; }
                }
            }
        }
    }
    // fallback ranges rescan memory (not taken at n = 12288)
    for (int i4 = regEnd + tid; i4 < nf4; i4 += TPB) {
        float4 v = seg4[i4];
        float xs[4] = {v.x, v.y, v.z, v.w};
#pragma unroll
        for (int c = 0; c < 4; c++) {
            if (xs[c] >= T) {
                int s = atomicAdd(&cnt, 1);
                if (s < CAP) { cv[s] = xs[c]; ci[s] = (i4 << 2) + c; }
            }
        }
    }
    for (int i = (nf4 << 2) + tid; i < n; i += TPB) {
        float x = segb[i];
        if (x >= T) {
            int s = atomicAdd(&cnt, 1);
            if (s < CAP) { cv[s] = x; ci[s] = i; }
        }
    }
    __syncthreads();

    // exact top-10 set by rank-counting among the ~12 collected
    {
        int mC = min(cnt, CAP);
        for (int i = tid; i < mC; i += TPB) {
            float v = cv[i]; int id = ci[i];
            int rank = 0;
            for (int j = 0; j < mC; j++) {
                float vj = cv[j];
                rank += (vj > v) || (vj == v && ci[j] < id);
            }
            if (rank < KC) topi[rank] = id;
        }
    }
    __syncthreads();

    // ---------------- build candidates (90 threads) ----------------
    if (tid < NKP * KC) {
        int i  = tid / KC;           // keypoint
        int j  = tid % KC;           // candidate
        int id = topi[j];
        const float* p = pcld + ((long long)b * n + id) * 3;
        const float* o = (i < 8)
            ? (kpts + (((long long)b * n + id) * 8 + i) * 3)
            : (cpt  + ((long long)b * n + id) * 3);
        cand[i][j][0] = p[0] + o[0];
        cand[i][j][1] = p[1] + o[1];
        cand[i][j][2] = p[2] + o[2];
    }
    __syncthreads();

    // ---------------- clustering with std filter (9 threads) ----------------
    if (tid < NKP) {
        float m0 = 0.f, m1 = 0.f, m2 = 0.f;
#pragma unroll
        for (int j = 0; j < KC; j++) { m0 += cand[tid][j][0]; m1 += cand[tid][j][1]; m2 += cand[tid][j][2]; }
        m0 *= 0.1f; m1 *= 0.1f; m2 *= 0.1f;
        float v0 = 0.f, v1 = 0.f, v2 = 0.f;
#pragma unroll
        for (int j = 0; j < KC; j++) {
            float d0 = cand[tid][j][0] - m0, d1 = cand[tid][j][1] - m1, d2 = cand[tid][j][2] - m2;
            v0 += d0 * d0; v1 += d1 * d1; v2 += d2 * d2;
        }
        float s0 = sqrtf(v0 * 0.1f), s1 = sqrtf(v1 * 0.1f), s2 = sqrtf(v2 * 0.1f);
        float a0 = 0.f, a1 = 0.f, a2 = 0.f, cc = 0.f;
#pragma unroll
        for (int j = 0; j < KC; j++) {
            float c0 = cand[tid][j][0], c1 = cand[tid][j][1], c2 = cand[tid][j][2];
            bool in = (fabsf(c0 - m0) <= s0) && (fabsf(c1 - m1) <= s1) && (fabsf(c2 - m2) <= s2);
            if (in) { cc += 1.f; a0 += c0; a1 += c1; a2 += c2; }
        }
        float inv = __fdividef(1.0f, cc + 1e-6f);
        float w0 = a0 * inv, w1 = a1 * inv, w2 = a2 * inv;
        voted[tid][0] = w0; voted[tid][1] = w1; voted[tid][2] = w2;
        long long vo = ((long long)b * NKP + tid) * 3;
        outV[vo + 0] = w0; outV[vo + 1] = w1; outV[vo + 2] = w2;
    }
    __syncthreads();

    // ---------------- Kabsch + closed-form 3x3 eigen (thread 0) ----------------
    if (tid == 0) {
        float cA[3] = {0, 0, 0}, cB[3] = {0, 0, 0};
#pragma unroll
        for (int i = 0; i < NKP; i++) {
            cA[0] += smesh[i * 3 + 0]; cA[1] += smesh[i * 3 + 1]; cA[2] += smesh[i * 3 + 2];
            cB[0] += voted[i][0];      cB[1] += voted[i][1];      cB[2] += voted[i][2];
        }
        const float inv9 = 1.0f / 9.0f;
        cA[0] *= inv9; cA[1] *= inv9; cA[2] *= inv9;
        cB[0] *= inv9; cB[1] *= inv9; cB[2] *= inv9;

        float H[3][3] = {{0,0,0},{0,0,0},{0,0,0}};
#pragma unroll
        for (int i = 0; i < NKP; i++) {
            float am[3] = {smesh[i*3+0] - cA[0], smesh[i*3+1] - cA[1], smesh[i*3+2] - cA[2]};
            float bm[3] = {voted[i][0] - cB[0], voted[i][1] - cB[1], voted[i][2] - cB[2]};
#pragma unroll
            for (int r = 0; r < 3; r++)
#pragma unroll
                for (int c = 0; c < 3; c++)
                    H[r][c] += am[r] * bm[c];
        }

        // K = H^T H (symmetric, PSD)
        float K[3][3];
#pragma unroll
        for (int r = 0; r < 3; r++)
#pragma unroll
            for (int c = 0; c < 3; c++)
                K[r][c] = H[0][r]*H[0][c] + H[1][r]*H[1][c] + H[2][r]*H[2][c];

        // closed-form symmetric eigenvalues (Smith): e1 >= e2 >= e3
        float v1[3] = {1.f, 0.f, 0.f}, v2[3] = {0.f, 1.f, 0.f};
        {
            float q  = (K[0][0] + K[1][1] + K[2][2]) * (1.0f / 3.0f);
            float p1 = K[0][1]*K[0][1] + K[0][2]*K[0][2] + K[1][2]*K[1][2];
            float b0 = K[0][0] - q, b1 = K[1][1] - q, b2 = K[2][2] - q;
            float p2 = b0*b0 + b1*b1 + b2*b2 + 2.0f * p1;
            if (p2 > 1e-30f) {
                float pp   = p2 * (1.0f / 6.0f);
                float invp = __frsqrt_rn(pp);
                float p    = pp * invp;                 // sqrt(p2/6)
                // det(B)/2 with B = (K - qI)/p
                float detB = b0 * (b1*b2 - K[1][2]*K[1][2])
                           - K[0][1] * (K[0][1]*b2 - K[1][2]*K[0][2])
                           + K[0][2] * (K[0][1]*K[1][2] - b1*K[0][2]);
                float r = detB * 0.5f * invp * invp * invp;
                r = fminf(1.0f, fmaxf(-1.0f, r));
                float phi = acos_poly(r) * (1.0f / 3.0f);
                float e1 = q + 2.0f * p * __cosf(phi);
                float e3 = q + 2.0f * p * __cosf(phi + 2.0943951023931953f);
                float e2 = 3.0f * q - e1 - e3;
                eigvec3(K, e1, v1);
                eigvec3(K, e2, v2);
                // re-orthogonalize v2 against v1 (robust near-degenerate gaps)
                float d = v2[0]*v1[0] + v2[1]*v1[1] + v2[2]*v1[2];
                v2[0] -= d * v1[0]; v2[1] -= d * v1[1]; v2[2] -= d * v1[2];
                float nn = v2[0]*v2[0] + v2[1]*v2[1] + v2[2]*v2[2];
                float ii = (nn > 1e-30f) ? __frsqrt_rn(nn) : 0.0f;
                v2[0] *= ii; v2[1] *= ii; v2[2] *= ii;
            }
        }
        float v3[3] = { v1[1]*v2[2] - v1[2]*v2[1],
                        v1[2]*v2[0] - v1[0]*v2[2],
                        v1[0]*v2[1] - v1[1]*v2[0] };

        float u1[3], u2[3], u3[3];
#pragma unroll
        for (int r = 0; r < 3; r++) u1[r] = H[r][0]*v1[0] + H[r][1]*v1[1] + H[r][2]*v1[2];
        float d1 = u1[0]*u1[0] + u1[1]*u1[1] + u1[2]*u1[2];
        float in1 = (d1 > 1e-30f) ? __frsqrt_rn(d1) : 0.0f;
        u1[0] *= in1; u1[1] *= in1; u1[2] *= in1;

#pragma unroll
        for (int r = 0; r < 3; r++) u2[r] = H[r][0]*v2[0] + H[r][1]*v2[1] + H[r][2]*v2[2];
        float d12 = u2[0]*u1[0] + u2[1]*u1[1] + u2[2]*u1[2];
        u2[0] -= d12 * u1[0]; u2[1] -= d12 * u1[1]; u2[2] -= d12 * u1[2];
        float d2 = u2[0]*u2[0] + u2[1]*u2[1] + u2[2]*u2[2];
        float in2 = (d2 > 1e-30f) ? __frsqrt_rn(d2) : 0.0f;
        u2[0] *= in2; u2[1] *= in2; u2[2] *= in2;

        u3[0] = u1[1]*u2[2] - u1[2]*u2[1];
        u3[1] = u1[2]*u2[0] - u1[0]*u2[2];
        u3[2] = u1[0]*u2[1] - u1[1]*u2[0];

        float R[3][3];
#pragma unroll
        for (int r = 0; r < 3; r++)
#pragma unroll
            for (int c = 0; c < 3; c++)
                R[r][c] = v1[r]*u1[c] + v2[r]*u2[c] + v3[r]*u3[c];

        float det = R[0][0]*(R[1][1]*R[2][2] - R[1][2]*R[2][1])
                  - R[0][1]*(R[1][0]*R[2][2] - R[1][2]*R[2][0])
                  + R[0][2]*(R[1][0]*R[2][1] - R[1][1]*R[2][0]);
        if (det < 0.0f) {
#pragma unroll
            for (int r = 0; r < 3; r++)
#pragma unroll
                for (int c = 0; c < 3; c++)
                    R[r][c] -= 2.0f * v3[r] * u3[c];
        }

        long long ro = (long long)b * 9;
#pragma unroll
        for (int r = 0; r < 3; r++)
#pragma unroll
            for (int c = 0; c < 3; c++)
                outR[ro + r*3 + c] = R[r][c];

        long long to = (long long)b * 3;
#pragma unroll
        for (int c = 0; c < 3; c++) {
            float tc = cB[c] - (R[c][0]*cA[0] + R[c][1]*cA[1] + R[c][2]*cA[2]);
            outT[to + c] = tc;
        }
    }
}

extern "C" void kernel_launch(void* const* d_in, const int* in_sizes, int n_in,
                              void* d_out, int out_size)
{
    const float* pcld = (const float*)d_in[0];  // [b,n,3]
    const float* kpts = (const float*)d_in[1];  // [b,n,8,3]
    const float* cpt  = (const float*)d_in[2];  // [b,n,1,3]
    const float* seg  = (const float*)d_in[3];  // [b,n,1]
    const float* mesh = (const float*)d_in[4];  // [b,9,3]

    int b = in_sizes[4] / 27;       // mesh is b*9*3
    int n = in_sizes[3] / b;        // seg is b*n

    float* out  = (float*)d_out;
    float* outR = out;                      // b*9
    float* outT = out + (long long)b * 9;   // b*3
    float* outV = out + (long long)b * 12;  // b*27

    pose_fused_kernel<<<b, TPB>>>(pcld, kpts, cpt, seg, mesh, outR, outT, outV, n);
}